// round 1
// baseline (speedup 1.0000x reference)
#include <cuda_runtime.h>
#include <cstdint>

#define N 8192
#define D 512

static __device__ float g_dist[(size_t)N * N];   // 256 MB scratch
static __device__ float g_sqn[N];

// ---------------------------------------------------------------------------
// Kernel 1: squared norms (one warp per row) + zero the scalar output
// ---------------------------------------------------------------------------
__global__ void sqnorm_kernel(const float* __restrict__ emb, float* __restrict__ out) {
    if (blockIdx.x == 0 && threadIdx.x == 0) *out = 0.0f;
    int gwarp = (blockIdx.x * blockDim.x + threadIdx.x) >> 5;
    int lane  = threadIdx.x & 31;
    if (gwarp >= N) return;
    const float* r = emb + (size_t)gwarp * D;
    float s = 0.0f;
#pragma unroll
    for (int q = 0; q < D / 32; q++) {
        float v = r[lane + q * 32];
        s = fmaf(v, v, s);
    }
#pragma unroll
    for (int o = 16; o > 0; o >>= 1) s += __shfl_down_sync(0xffffffffu, s, o);
    if (lane == 0) g_sqn[gwarp] = s;
}

// ---------------------------------------------------------------------------
// Kernel 2: distance matrix via tiled fp32 GEMM (E @ E^T), fused epilogue.
// 128x128 block tile, BK=16, 8x8 per thread, double-buffered smem.
// ---------------------------------------------------------------------------
__global__ __launch_bounds__(256, 2) void dist_gemm(const float* __restrict__ emb) {
    __shared__ float As[2][16][128];
    __shared__ float Bs[2][16][128];

    const int tid = threadIdx.x;
    const int tx  = tid & 15;
    const int ty  = tid >> 4;
    const int i0  = blockIdx.y * 128;
    const int j0  = blockIdx.x * 128;

    // global-load mapping: each thread loads 2 float4 per operand tile
    const int lr = tid >> 2;         // row 0..63 (+64 for second float4)
    const int lc = (tid & 3) * 4;    // col 0,4,8,12

    const float* Ab = emb + (size_t)(i0 + lr) * D + lc;
    const float* Bb = emb + (size_t)(j0 + lr) * D + lc;

    float acc[8][8];
#pragma unroll
    for (int m = 0; m < 8; m++)
#pragma unroll
        for (int n = 0; n < 8; n++) acc[m][n] = 0.0f;

    float4 a0, a1, b0, b1;
    a0 = *(const float4*)(Ab);
    a1 = *(const float4*)(Ab + (size_t)64 * D);
    b0 = *(const float4*)(Bb);
    b1 = *(const float4*)(Bb + (size_t)64 * D);
#pragma unroll
    for (int q = 0; q < 4; q++) {
        As[0][lc + q][lr]      = ((const float*)&a0)[q];
        As[0][lc + q][lr + 64] = ((const float*)&a1)[q];
        Bs[0][lc + q][lr]      = ((const float*)&b0)[q];
        Bs[0][lc + q][lr + 64] = ((const float*)&b1)[q];
    }
    __syncthreads();

    const int NKT = D / 16;  // 32
    for (int kt = 0; kt < NKT; kt++) {
        const int cur = kt & 1;
        if (kt < NKT - 1) {
            const float* An = Ab + (kt + 1) * 16;
            const float* Bn = Bb + (kt + 1) * 16;
            a0 = *(const float4*)(An);
            a1 = *(const float4*)(An + (size_t)64 * D);
            b0 = *(const float4*)(Bn);
            b1 = *(const float4*)(Bn + (size_t)64 * D);
        }
#pragma unroll
        for (int k = 0; k < 16; k++) {
            float af[8], bf[8];
            *(float4*)&af[0] = *(const float4*)&As[cur][k][ty * 8];
            *(float4*)&af[4] = *(const float4*)&As[cur][k][ty * 8 + 4];
            *(float4*)&bf[0] = *(const float4*)&Bs[cur][k][tx * 8];
            *(float4*)&bf[4] = *(const float4*)&Bs[cur][k][tx * 8 + 4];
#pragma unroll
            for (int m = 0; m < 8; m++)
#pragma unroll
                for (int n = 0; n < 8; n++)
                    acc[m][n] = fmaf(af[m], bf[n], acc[m][n]);
        }
        if (kt < NKT - 1) {
            const int nxt = cur ^ 1;
#pragma unroll
            for (int q = 0; q < 4; q++) {
                As[nxt][lc + q][lr]      = ((const float*)&a0)[q];
                As[nxt][lc + q][lr + 64] = ((const float*)&a1)[q];
                Bs[nxt][lc + q][lr]      = ((const float*)&b0)[q];
                Bs[nxt][lc + q][lr + 64] = ((const float*)&b1)[q];
            }
            __syncthreads();
        }
    }

    // epilogue: d_ij = |xi|^2 + |xj|^2 - 2 xi.xj  (+1e10 on diagonal)
    float sqj[8];
#pragma unroll
    for (int n = 0; n < 8; n++) sqj[n] = g_sqn[j0 + tx * 8 + n];

#pragma unroll
    for (int m = 0; m < 8; m++) {
        const int i = i0 + ty * 8 + m;
        const float sqi = g_sqn[i];
        float r[8];
#pragma unroll
        for (int n = 0; n < 8; n++) {
            const int j = j0 + tx * 8 + n;
            float v = sqi + sqj[n] - 2.0f * acc[m][n];
            if (i == j) v += 10000000000.0f;
            r[n] = v;
        }
        float* dst = g_dist + (size_t)i * N + j0 + tx * 8;
        *(float4*)(dst)     = *(const float4*)&r[0];
        *(float4*)(dst + 4) = *(const float4*)&r[4];
    }
}

// ---------------------------------------------------------------------------
// Kernel 3: per-row top-15 selection + softmax*mask weights + batch entropy
// One block (256 threads) per row.
// ---------------------------------------------------------------------------
__global__ __launch_bounds__(256) void row_kernel(const int* __restrict__ labels,
                                                  float* __restrict__ out) {
    const int row = blockIdx.x;
    const int tid = threadIdx.x;
    const float* dr = g_dist + (size_t)row * N;

    __shared__ float cand[256 * 15];
    __shared__ float rv[256];
    __shared__ int   ri[256];
    __shared__ float s_dmin, s_kth;
    __shared__ float wr[5][8];

    const float INF = __int_as_float(0x7f800000);

    // phase 1: per-thread sorted top-15 over strided slice (32 elems)
    float loc[15];
#pragma unroll
    for (int q = 0; q < 15; q++) loc[q] = INF;
    for (int it = 0; it < N / 256; it++) {
        float v = dr[tid + it * 256];
        if (v < loc[14]) {
            loc[14] = v;
#pragma unroll
            for (int q = 14; q > 0; q--) {
                if (loc[q] < loc[q - 1]) {
                    float t = loc[q - 1]; loc[q - 1] = loc[q]; loc[q] = t;
                }
            }
        }
    }
#pragma unroll
    for (int q = 0; q < 15; q++) cand[tid * 15 + q] = loc[q];

    // phase 2: 15 rounds of block argmin extraction (exact multiset semantics)
    int p = 0;
    for (int round = 0; round < 15; round++) {
        float c = (p < 15) ? cand[tid * 15 + p] : INF;
        rv[tid] = c;
        ri[tid] = tid;
        __syncthreads();
        for (int s = 128; s > 0; s >>= 1) {
            if (tid < s) {
                if (rv[tid + s] < rv[tid]) { rv[tid] = rv[tid + s]; ri[tid] = ri[tid + s]; }
            }
            __syncthreads();
        }
        if (tid == 0) {
            if (round == 0)  s_dmin = rv[0];
            if (round == 14) s_kth  = rv[0];
        }
        if (tid == ri[0]) p++;
        __syncthreads();
    }
    const float dmin = s_dmin;
    const float kth  = s_kth;

    // phase 3: weights + per-batch accumulation
    float Z = 0.f, S = 0.f, s0 = 0.f, s1 = 0.f, s2 = 0.f;
    for (int it = 0; it < N / 256; it++) {
        int j = tid + it * 256;
        float d = dr[j];
        float e  = __expf(dmin - d);                 // softmax numerator (shifted)
        float km = 1.0f / (1.0f + __expf(d - kth));  // sigmoid((kth - d)/T)
        float t  = e * km;
        Z += e;
        S += t;
        int lb = labels[j];
        s0 += (lb == 0) ? t : 0.0f;
        s1 += (lb == 1) ? t : 0.0f;
        s2 += (lb == 2) ? t : 0.0f;
    }
#pragma unroll
    for (int o = 16; o > 0; o >>= 1) {
        Z  += __shfl_down_sync(0xffffffffu, Z,  o);
        S  += __shfl_down_sync(0xffffffffu, S,  o);
        s0 += __shfl_down_sync(0xffffffffu, s0, o);
        s1 += __shfl_down_sync(0xffffffffu, s1, o);
        s2 += __shfl_down_sync(0xffffffffu, s2, o);
    }
    const int lane = tid & 31, wid = tid >> 5;
    if (lane == 0) {
        wr[0][wid] = Z; wr[1][wid] = S; wr[2][wid] = s0; wr[3][wid] = s1; wr[4][wid] = s2;
    }
    __syncthreads();
    if (tid == 0) {
        float Zt = 0, St = 0, t0 = 0, t1 = 0, t2 = 0;
#pragma unroll
        for (int w = 0; w < 8; w++) {
            Zt += wr[0][w]; St += wr[1][w]; t0 += wr[2][w]; t1 += wr[3][w]; t2 += wr[4][w];
        }
        // w_j = t_j / (S + eps*Z)  (== softmax*mask renormalized, eps=1e-8)
        float denom = St + 1e-8f * Zt;
        float p0 = t0 / denom, p1 = t1 / denom, p2 = t2 / denom;
        float H = -(p0 * logf(p0 + 1e-8f) + p1 * logf(p1 + 1e-8f) + p2 * logf(p2 + 1e-8f));
        float nH = H / (logf(3.0f) + 1e-8f);
        atomicAdd(out, -nH * (1.0f / N));
    }
}

// ---------------------------------------------------------------------------
extern "C" void kernel_launch(void* const* d_in, const int* in_sizes, int n_in,
                              void* d_out, int out_size) {
    const float* emb    = (const float*)d_in[0];
    const int*   labels = (const int*)d_in[1];
    float*       out    = (float*)d_out;

    sqnorm_kernel<<<N / 8, 256>>>(emb, out);     // 1024 blocks x 8 warps
    dim3 g(N / 128, N / 128);                    // 64 x 64
    dist_gemm<<<g, 256>>>(emb);
    row_kernel<<<N, 256>>>(labels, out);
}

// round 5
// speedup vs baseline: 2.6223x; 2.6223x over previous
#include <cuda_runtime.h>
#include <cuda_bf16.h>
#include <cstdint>

#define N 8192
#define D 512

static __device__ float g_dist[(size_t)N * N];   // 256 MB scratch
static __device__ float g_sqn[N];
static __device__ __nv_bfloat16 g_hi[(size_t)N * D];
static __device__ __nv_bfloat16 g_lo[(size_t)N * D];

// ---------------------------------------------------------------------------
// helpers
// ---------------------------------------------------------------------------
__device__ __forceinline__ uint32_t smem_u32(const void* p) {
    uint32_t a;
    asm("{ .reg .u64 t; cvta.to.shared.u64 t, %1; cvt.u32.u64 %0, t; }" : "=r"(a) : "l"(p));
    return a;
}
__device__ __forceinline__ uint32_t sw128(uint32_t b) { return b ^ ((b >> 3) & 0x70); }

__device__ __forceinline__ void cp16(uint32_t dst, const void* src) {
    asm volatile("cp.async.cg.shared.global [%0], [%1], 16;" :: "r"(dst), "l"(src));
}
#define CP_COMMIT() asm volatile("cp.async.commit_group;" ::: "memory")
#define CP_WAIT0()  asm volatile("cp.async.wait_group 0;" ::: "memory")
#define CP_WAIT1()  asm volatile("cp.async.wait_group 1;" ::: "memory")

__device__ __forceinline__ void ldsm_x4(uint32_t* r, uint32_t addr) {
    asm volatile("ldmatrix.sync.aligned.m8n8.x4.shared.b16 {%0,%1,%2,%3}, [%4];"
                 : "=r"(r[0]), "=r"(r[1]), "=r"(r[2]), "=r"(r[3]) : "r"(addr));
}
__device__ __forceinline__ void mma16816(float* d, const uint32_t* a, uint32_t b0, uint32_t b1) {
    asm volatile(
        "mma.sync.aligned.m16n8k16.row.col.f32.bf16.bf16.f32 "
        "{%0,%1,%2,%3}, {%4,%5,%6,%7}, {%8,%9}, {%0,%1,%2,%3};"
        : "+f"(d[0]), "+f"(d[1]), "+f"(d[2]), "+f"(d[3])
        : "r"(a[0]), "r"(a[1]), "r"(a[2]), "r"(a[3]), "r"(b0), "r"(b1));
}

// ---------------------------------------------------------------------------
// Kernel 1: sqnorms + fp32 -> bf16 hi/lo split (one warp per row), zero out
// ---------------------------------------------------------------------------
__global__ void prep_kernel(const float* __restrict__ emb, float* __restrict__ out) {
    if (blockIdx.x == 0 && threadIdx.x == 0) *out = 0.0f;
    int gw   = (blockIdx.x * blockDim.x + threadIdx.x) >> 5;
    int lane = threadIdx.x & 31;
    if (gw >= N) return;
    const float4* src = (const float4*)(emb + (size_t)gw * D);
    float s = 0.0f;
#pragma unroll
    for (int q = 0; q < 4; q++) {
        float4 v = src[lane + q * 32];
        s = fmaf(v.x, v.x, fmaf(v.y, v.y, fmaf(v.z, v.z, fmaf(v.w, v.w, s))));
        __nv_bfloat16 h[4], l[4];
        float f[4] = {v.x, v.y, v.z, v.w};
#pragma unroll
        for (int u = 0; u < 4; u++) {
            h[u] = __float2bfloat16(f[u]);
            l[u] = __float2bfloat16(f[u] - __bfloat162float(h[u]));
        }
        size_t off = (size_t)gw * D + lane * 4 + q * 128;
        *(uint2*)(g_hi + off) = *(const uint2*)h;
        *(uint2*)(g_lo + off) = *(const uint2*)l;
    }
#pragma unroll
    for (int o = 16; o > 0; o >>= 1) s += __shfl_down_sync(0xffffffffu, s, o);
    if (lane == 0) g_sqn[gw] = s;
}

// ---------------------------------------------------------------------------
// Kernel 2: 128x128-tile symmetric distance GEMM via mma.sync bf16-split.
// Upper-triangle tiles (2080 CTAs), mirror through smem transpose.
// ---------------------------------------------------------------------------
#define STAGE_BYTES 32768          // A 16KB + B 16KB per K=64 chunk
#define SST 132                    // smem transpose row stride (floats)
#define GEMM_SMEM (128 * SST * 4)  // 67584 >= 2*STAGE_BYTES
#define NCHUNK 24                  // 3 passes x 8 chunks

__device__ __forceinline__ void load_chunk(int c, uint32_t st, int i0, int j0, int tid) {
    const int pass = c >> 3, kc = c & 7;
    const __nv_bfloat16* Asrc = (pass == 2) ? g_lo : g_hi;
    const __nv_bfloat16* Bsrc = (pass == 1) ? g_lo : g_hi;
#pragma unroll
    for (int q = 0; q < 4; q++) {
        int idx = q * 256 + tid;
        int row = idx >> 3, seg = idx & 7;
        cp16(st + sw128(row * 128 + seg * 16),
             Asrc + (size_t)(i0 + row) * D + kc * 64 + seg * 8);
    }
#pragma unroll
    for (int q = 0; q < 4; q++) {
        int idx = q * 256 + tid;
        int row = idx >> 3, seg = idx & 7;
        cp16(st + 16384 + sw128(row * 128 + seg * 16),
             Bsrc + (size_t)(j0 + row) * D + kc * 64 + seg * 8);
    }
    CP_COMMIT();
}

__global__ __launch_bounds__(256, 2) void gemm_kernel() {
    extern __shared__ __align__(1024) uint8_t dsm[];
    const int tid  = threadIdx.x;
    const int wid  = tid >> 5;
    const int lane = tid & 31;

    // upper-triangle tile decode (64x64 grid of 128-tiles)
    int t = blockIdx.x, bi = 0, rem = 64;
    while (t >= rem) { t -= rem; bi++; rem--; }
    const int bj = bi + t;
    const int i0 = bi * 128, j0 = bj * 128;

    const uint32_t dsm_b = smem_u32(dsm);
    const int wm = (wid >> 2) * 64;   // warp m-offset (0/64)
    const int wn = (wid & 3) * 32;    // warp n-offset (0/32/64/96)

    float acc[4][4][4];
#pragma unroll
    for (int a = 0; a < 4; a++)
#pragma unroll
        for (int b = 0; b < 4; b++)
#pragma unroll
            for (int k = 0; k < 4; k++) acc[a][b][k] = 0.0f;

    load_chunk(0, dsm_b, i0, j0, tid);

    const uint32_t lrow = lane & 15, lhalf = (lane >> 4) * 16;
    for (int c = 0; c < NCHUNK; c++) {
        const uint32_t stA = dsm_b + (c & 1) * STAGE_BYTES;
        const uint32_t stB = stA + 16384;
        if (c + 1 < NCHUNK) {
            load_chunk(c + 1, dsm_b + ((c + 1) & 1) * STAGE_BYTES, i0, j0, tid);
            CP_WAIT1();
        } else {
            CP_WAIT0();
        }
        __syncthreads();
#pragma unroll
        for (int kk = 0; kk < 4; kk++) {
            uint32_t afr[4][4], bfr[2][4];
#pragma unroll
            for (int mf = 0; mf < 4; mf++)
                ldsm_x4(afr[mf], stA + sw128((wm + mf * 16 + lrow) * 128 + kk * 32 + lhalf));
#pragma unroll
            for (int g = 0; g < 2; g++)
                ldsm_x4(bfr[g], stB + sw128((wn + g * 16 + lrow) * 128 + kk * 32 + lhalf));
#pragma unroll
            for (int mf = 0; mf < 4; mf++)
#pragma unroll
                for (int nf = 0; nf < 4; nf++)
                    mma16816(acc[mf][nf], afr[mf],
                             bfr[nf >> 1][nf & 1], bfr[nf >> 1][(nf & 1) + 2]);
        }
        __syncthreads();
    }

    // ---- epilogue: distances into smem transpose buffer, then coalesced writes
    float* smemf = (float*)dsm;
    const int qr = lane >> 2, qc = (lane & 3) * 2;
#pragma unroll
    for (int mf = 0; mf < 4; mf++) {
        const int r0 = wm + mf * 16 + qr;
        const float si0 = g_sqn[i0 + r0], si1 = g_sqn[i0 + r0 + 8];
#pragma unroll
        for (int nf = 0; nf < 4; nf++) {
            const int c0 = wn + nf * 8 + qc;
            const float sj0 = g_sqn[j0 + c0], sj1 = g_sqn[j0 + c0 + 1];
            const float* p = acc[mf][nf];
            float v00 = si0 + sj0 - 2.0f * p[0];
            float v01 = si0 + sj1 - 2.0f * p[1];
            float v10 = si1 + sj0 - 2.0f * p[2];
            float v11 = si1 + sj1 - 2.0f * p[3];
            if (i0 + r0     == j0 + c0)     v00 += 10000000000.0f;
            if (i0 + r0     == j0 + c0 + 1) v01 += 10000000000.0f;
            if (i0 + r0 + 8 == j0 + c0)     v10 += 10000000000.0f;
            if (i0 + r0 + 8 == j0 + c0 + 1) v11 += 10000000000.0f;
            smemf[r0 * SST + c0]           = v00;
            smemf[r0 * SST + c0 + 1]       = v01;
            smemf[(r0 + 8) * SST + c0]     = v10;
            smemf[(r0 + 8) * SST + c0 + 1] = v11;
        }
    }
    __syncthreads();

    {   // direct write: rows i, coalesced float4
        const int row = tid >> 1, seg = tid & 1;
        const float* sr = smemf + row * SST + seg * 64;
        float4* dst = (float4*)(g_dist + (size_t)(i0 + row) * N + j0 + seg * 64);
#pragma unroll
        for (int u = 0; u < 16; u++) dst[u] = *(const float4*)(sr + u * 4);
    }
    if (i0 != j0) {  // mirror write: rows j, gather smem columns
        const int jrow = tid >> 1, seg = tid & 1;
        float* dst = g_dist + (size_t)(j0 + jrow) * N + i0 + seg * 64;
#pragma unroll
        for (int u = 0; u < 16; u++) {
            float4 v;
            v.x = smemf[(seg * 64 + u * 4 + 0) * SST + jrow];
            v.y = smemf[(seg * 64 + u * 4 + 1) * SST + jrow];
            v.z = smemf[(seg * 64 + u * 4 + 2) * SST + jrow];
            v.w = smemf[(seg * 64 + u * 4 + 3) * SST + jrow];
            *(float4*)(dst + u * 4) = v;
        }
    }
}

// ---------------------------------------------------------------------------
// Kernel 3: per-row top-15 + softmax*mask weights + batch entropy
// ---------------------------------------------------------------------------
__global__ __launch_bounds__(256) void row_kernel(const int* __restrict__ labels,
                                                  float* __restrict__ out) {
    const int row = blockIdx.x;
    const int tid = threadIdx.x;
    const float* dr = g_dist + (size_t)row * N;

    __shared__ float cand[256 * 15];
    __shared__ float rv[256];
    __shared__ int   ri[256];
    __shared__ float s_dmin, s_kth;
    __shared__ float wr[5][8];

    const float INF = __int_as_float(0x7f800000);

    float loc[15];
#pragma unroll
    for (int q = 0; q < 15; q++) loc[q] = INF;
    for (int it = 0; it < N / 256; it++) {
        float v = dr[tid + it * 256];
        if (v < loc[14]) {
            loc[14] = v;
#pragma unroll
            for (int q = 14; q > 0; q--) {
                if (loc[q] < loc[q - 1]) {
                    float tt = loc[q - 1]; loc[q - 1] = loc[q]; loc[q] = tt;
                }
            }
        }
    }
#pragma unroll
    for (int q = 0; q < 15; q++) cand[tid * 15 + q] = loc[q];

    int p = 0;
    for (int round = 0; round < 15; round++) {
        float c = (p < 15) ? cand[tid * 15 + p] : INF;
        rv[tid] = c;
        ri[tid] = tid;
        __syncthreads();
        for (int s = 128; s > 0; s >>= 1) {
            if (tid < s) {
                if (rv[tid + s] < rv[tid]) { rv[tid] = rv[tid + s]; ri[tid] = ri[tid + s]; }
            }
            __syncthreads();
        }
        if (tid == 0) {
            if (round == 0)  s_dmin = rv[0];
            if (round == 14) s_kth  = rv[0];
        }
        if (tid == ri[0]) p++;
        __syncthreads();
    }
    const float dmin = s_dmin;
    const float kth  = s_kth;

    float Z = 0.f, S = 0.f, s0 = 0.f, s1 = 0.f, s2 = 0.f;
    for (int it = 0; it < N / 256; it++) {
        int j = tid + it * 256;
        float d = dr[j];
        float e  = __expf(dmin - d);
        float km = 1.0f / (1.0f + __expf(d - kth));
        float tt = e * km;
        Z += e;
        S += tt;
        int lb = labels[j];
        s0 += (lb == 0) ? tt : 0.0f;
        s1 += (lb == 1) ? tt : 0.0f;
        s2 += (lb == 2) ? tt : 0.0f;
    }
#pragma unroll
    for (int o = 16; o > 0; o >>= 1) {
        Z  += __shfl_down_sync(0xffffffffu, Z,  o);
        S  += __shfl_down_sync(0xffffffffu, S,  o);
        s0 += __shfl_down_sync(0xffffffffu, s0, o);
        s1 += __shfl_down_sync(0xffffffffu, s1, o);
        s2 += __shfl_down_sync(0xffffffffu, s2, o);
    }
    const int lane = tid & 31, wid = tid >> 5;
    if (lane == 0) {
        wr[0][wid] = Z; wr[1][wid] = S; wr[2][wid] = s0; wr[3][wid] = s1; wr[4][wid] = s2;
    }
    __syncthreads();
    if (tid == 0) {
        float Zt = 0, St = 0, t0 = 0, t1 = 0, t2 = 0;
#pragma unroll
        for (int w = 0; w < 8; w++) {
            Zt += wr[0][w]; St += wr[1][w]; t0 += wr[2][w]; t1 += wr[3][w]; t2 += wr[4][w];
        }
        float denom = St + 1e-8f * Zt;
        float p0 = t0 / denom, p1 = t1 / denom, p2 = t2 / denom;
        float H = -(p0 * logf(p0 + 1e-8f) + p1 * logf(p1 + 1e-8f) + p2 * logf(p2 + 1e-8f));
        float nH = H / (logf(3.0f) + 1e-8f);
        atomicAdd(out, -nH * (1.0f / N));
    }
}

// ---------------------------------------------------------------------------
extern "C" void kernel_launch(void* const* d_in, const int* in_sizes, int n_in,
                              void* d_out, int out_size) {
    const float* emb    = (const float*)d_in[0];
    const int*   labels = (const int*)d_in[1];
    float*       out    = (float*)d_out;

    cudaFuncSetAttribute(gemm_kernel, cudaFuncAttributeMaxDynamicSharedMemorySize, GEMM_SMEM);

    prep_kernel<<<N / 8, 256>>>(emb, out);
    gemm_kernel<<<64 * 65 / 2, 256, GEMM_SMEM>>>();   // 2080 upper-tri tiles
    row_kernel<<<N, 256>>>(labels, out);
}

// round 6
// speedup vs baseline: 2.9100x; 1.1097x over previous
#include <cuda_runtime.h>
#include <cuda_bf16.h>
#include <cstdint>

#define N 8192
#define D 512

static __device__ float g_dist[(size_t)N * N];   // 256 MB scratch
static __device__ float g_sqn[N];
static __device__ __nv_bfloat16 g_hi[(size_t)N * D];
static __device__ __nv_bfloat16 g_lo[(size_t)N * D];

// ---------------------------------------------------------------------------
// helpers
// ---------------------------------------------------------------------------
__device__ __forceinline__ uint32_t smem_u32(const void* p) {
    uint32_t a;
    asm("{ .reg .u64 t; cvta.to.shared.u64 t, %1; cvt.u32.u64 %0, t; }" : "=r"(a) : "l"(p));
    return a;
}
__device__ __forceinline__ uint32_t sw128(uint32_t b) { return b ^ ((b >> 3) & 0x70); }

__device__ __forceinline__ void cp16(uint32_t dst, const void* src) {
    asm volatile("cp.async.cg.shared.global [%0], [%1], 16;" :: "r"(dst), "l"(src));
}
#define CP_COMMIT() asm volatile("cp.async.commit_group;" ::: "memory")
#define CP_WAIT0()  asm volatile("cp.async.wait_group 0;" ::: "memory")
#define CP_WAIT1()  asm volatile("cp.async.wait_group 1;" ::: "memory")

__device__ __forceinline__ void ldsm_x4(uint32_t* r, uint32_t addr) {
    asm volatile("ldmatrix.sync.aligned.m8n8.x4.shared.b16 {%0,%1,%2,%3}, [%4];"
                 : "=r"(r[0]), "=r"(r[1]), "=r"(r[2]), "=r"(r[3]) : "r"(addr));
}
__device__ __forceinline__ void mma16816(float* d, const uint32_t* a, uint32_t b0, uint32_t b1) {
    asm volatile(
        "mma.sync.aligned.m16n8k16.row.col.f32.bf16.bf16.f32 "
        "{%0,%1,%2,%3}, {%4,%5,%6,%7}, {%8,%9}, {%0,%1,%2,%3};"
        : "+f"(d[0]), "+f"(d[1]), "+f"(d[2]), "+f"(d[3])
        : "r"(a[0]), "r"(a[1]), "r"(a[2]), "r"(a[3]), "r"(b0), "r"(b1));
}

// ---------------------------------------------------------------------------
// Kernel 1: sqnorms + fp32 -> bf16 hi/lo split (one warp per row), zero out
// ---------------------------------------------------------------------------
__global__ void prep_kernel(const float* __restrict__ emb, float* __restrict__ out) {
    if (blockIdx.x == 0 && threadIdx.x == 0) *out = 0.0f;
    int gw   = (blockIdx.x * blockDim.x + threadIdx.x) >> 5;
    int lane = threadIdx.x & 31;
    if (gw >= N) return;
    const float4* src = (const float4*)(emb + (size_t)gw * D);
    float s = 0.0f;
#pragma unroll
    for (int q = 0; q < 4; q++) {
        float4 v = src[lane + q * 32];
        s = fmaf(v.x, v.x, fmaf(v.y, v.y, fmaf(v.z, v.z, fmaf(v.w, v.w, s))));
        __nv_bfloat16 h[4], l[4];
        float f[4] = {v.x, v.y, v.z, v.w};
#pragma unroll
        for (int u = 0; u < 4; u++) {
            h[u] = __float2bfloat16(f[u]);
            l[u] = __float2bfloat16(f[u] - __bfloat162float(h[u]));
        }
        size_t off = (size_t)gw * D + lane * 4 + q * 128;
        *(uint2*)(g_hi + off) = *(const uint2*)h;
        *(uint2*)(g_lo + off) = *(const uint2*)l;
    }
#pragma unroll
    for (int o = 16; o > 0; o >>= 1) s += __shfl_down_sync(0xffffffffu, s, o);
    if (lane == 0) g_sqn[gw] = s;
}

// ---------------------------------------------------------------------------
// Kernel 2: 128x128-tile symmetric distance GEMM via mma.sync bf16-split.
// Upper-triangle tiles (2080 CTAs), 3-stage cp.async pipeline, mirror writes.
// ---------------------------------------------------------------------------
#define STAGE_BYTES 32768          // A 16KB + B 16KB per K=64 chunk
#define NSTAGE 3
#define SST 132                    // smem transpose row stride (floats)
#define GEMM_SMEM (NSTAGE * STAGE_BYTES)  // 98304 >= 128*SST*4 = 67584
#define NCHUNK 24                  // 3 passes x 8 chunks

__device__ __forceinline__ void load_chunk(int c, uint32_t st, int i0, int j0, int tid) {
    const int pass = c >> 3, kc = c & 7;
    const __nv_bfloat16* Asrc = (pass == 2) ? g_lo : g_hi;
    const __nv_bfloat16* Bsrc = (pass == 1) ? g_lo : g_hi;
#pragma unroll
    for (int q = 0; q < 4; q++) {
        int idx = q * 256 + tid;
        int row = idx >> 3, seg = idx & 7;
        cp16(st + sw128(row * 128 + seg * 16),
             Asrc + (size_t)(i0 + row) * D + kc * 64 + seg * 8);
    }
#pragma unroll
    for (int q = 0; q < 4; q++) {
        int idx = q * 256 + tid;
        int row = idx >> 3, seg = idx & 7;
        cp16(st + 16384 + sw128(row * 128 + seg * 16),
             Bsrc + (size_t)(j0 + row) * D + kc * 64 + seg * 8);
    }
    CP_COMMIT();
}

__global__ __launch_bounds__(256, 2) void gemm_kernel() {
    extern __shared__ __align__(1024) uint8_t dsm[];
    const int tid  = threadIdx.x;
    const int wid  = tid >> 5;
    const int lane = tid & 31;

    // upper-triangle tile decode (64x64 grid of 128-tiles)
    int t = blockIdx.x, bi = 0, rem = 64;
    while (t >= rem) { t -= rem; bi++; rem--; }
    const int bj = bi + t;
    const int i0 = bi * 128, j0 = bj * 128;

    const uint32_t dsm_b = smem_u32(dsm);
    const int wm = (wid >> 2) * 64;   // warp m-offset (0/64)
    const int wn = (wid & 3) * 32;    // warp n-offset (0/32/64/96)

    float acc[4][4][4];
#pragma unroll
    for (int a = 0; a < 4; a++)
#pragma unroll
        for (int b = 0; b < 4; b++)
#pragma unroll
            for (int k = 0; k < 4; k++) acc[a][b][k] = 0.0f;

    // prologue: stages 0,1 in flight
    load_chunk(0, dsm_b, i0, j0, tid);
    load_chunk(1, dsm_b + STAGE_BYTES, i0, j0, tid);

    const uint32_t lrow = lane & 15, lhalf = (lane >> 4) * 16;
    int slot = 0;                          // slot(c) = c % 3
    for (int c = 0; c < NCHUNK; c++) {
        if (c + 1 < NCHUNK) CP_WAIT1(); else CP_WAIT0();  // stage c arrived (this thread)
        __syncthreads();                                   // all threads' stage c visible
        if (c + 2 < NCHUNK) {
            int ns = slot + 2; if (ns >= NSTAGE) ns -= NSTAGE;
            load_chunk(c + 2, dsm_b + ns * STAGE_BYTES, i0, j0, tid);
        }
        const uint32_t stA = dsm_b + slot * STAGE_BYTES;
        const uint32_t stB = stA + 16384;
#pragma unroll
        for (int kk = 0; kk < 4; kk++) {
            uint32_t afr[4][4], bfr[2][4];
#pragma unroll
            for (int mf = 0; mf < 4; mf++)
                ldsm_x4(afr[mf], stA + sw128((wm + mf * 16 + lrow) * 128 + kk * 32 + lhalf));
#pragma unroll
            for (int g = 0; g < 2; g++)
                ldsm_x4(bfr[g], stB + sw128((wn + g * 16 + lrow) * 128 + kk * 32 + lhalf));
#pragma unroll
            for (int mf = 0; mf < 4; mf++)
#pragma unroll
                for (int nf = 0; nf < 4; nf++)
                    mma16816(acc[mf][nf], afr[mf],
                             bfr[nf >> 1][nf & 1], bfr[nf >> 1][(nf & 1) + 2]);
        }
        if (++slot == NSTAGE) slot = 0;
    }
    __syncthreads();   // everyone done reading stages before smem reuse

    // ---- epilogue: distances into smem transpose buffer, then coalesced writes
    float* smemf = (float*)dsm;
    const int qr = lane >> 2, qc = (lane & 3) * 2;
#pragma unroll
    for (int mf = 0; mf < 4; mf++) {
        const int r0 = wm + mf * 16 + qr;
        const float si0 = g_sqn[i0 + r0], si1 = g_sqn[i0 + r0 + 8];
#pragma unroll
        for (int nf = 0; nf < 4; nf++) {
            const int c0 = wn + nf * 8 + qc;
            const float sj0 = g_sqn[j0 + c0], sj1 = g_sqn[j0 + c0 + 1];
            const float* p = acc[mf][nf];
            float v00 = si0 + sj0 - 2.0f * p[0];
            float v01 = si0 + sj1 - 2.0f * p[1];
            float v10 = si1 + sj0 - 2.0f * p[2];
            float v11 = si1 + sj1 - 2.0f * p[3];
            if (i0 + r0     == j0 + c0)     v00 += 10000000000.0f;
            if (i0 + r0     == j0 + c0 + 1) v01 += 10000000000.0f;
            if (i0 + r0 + 8 == j0 + c0)     v10 += 10000000000.0f;
            if (i0 + r0 + 8 == j0 + c0 + 1) v11 += 10000000000.0f;
            smemf[r0 * SST + c0]           = v00;
            smemf[r0 * SST + c0 + 1]       = v01;
            smemf[(r0 + 8) * SST + c0]     = v10;
            smemf[(r0 + 8) * SST + c0 + 1] = v11;
        }
    }
    __syncthreads();

    {   // direct write: rows i, coalesced float4
        const int row = tid >> 1, seg = tid & 1;
        const float* sr = smemf + row * SST + seg * 64;
        float4* dst = (float4*)(g_dist + (size_t)(i0 + row) * N + j0 + seg * 64);
#pragma unroll
        for (int u = 0; u < 16; u++) dst[u] = *(const float4*)(sr + u * 4);
    }
    if (i0 != j0) {  // mirror write: rows j, gather smem columns
        const int jrow = tid >> 1, seg = tid & 1;
        float* dst = g_dist + (size_t)(j0 + jrow) * N + i0 + seg * 64;
#pragma unroll
        for (int u = 0; u < 16; u++) {
            float4 v;
            v.x = smemf[(seg * 64 + u * 4 + 0) * SST + jrow];
            v.y = smemf[(seg * 64 + u * 4 + 1) * SST + jrow];
            v.z = smemf[(seg * 64 + u * 4 + 2) * SST + jrow];
            v.w = smemf[(seg * 64 + u * 4 + 3) * SST + jrow];
            *(float4*)(dst + u * 4) = v;
        }
    }
}

// ---------------------------------------------------------------------------
// Kernel 3: warp-per-row top-15 + softmax*mask weights + batch entropy.
// 8 rows per 256-thread CTA; no block barriers in the hot path.
// ---------------------------------------------------------------------------
__device__ __forceinline__ void ins15(float loc[15], float v) {
    if (v < loc[14]) {
        loc[14] = v;
#pragma unroll
        for (int q = 14; q > 0; q--) {
            if (loc[q] < loc[q - 1]) { float tt = loc[q - 1]; loc[q - 1] = loc[q]; loc[q] = tt; }
        }
    }
}

__global__ __launch_bounds__(256) void row_kernel(const int* __restrict__ labels,
                                                  float* __restrict__ out) {
    const int tid  = threadIdx.x;
    const int wid  = tid >> 5;
    const int lane = tid & 31;
    const int row  = blockIdx.x * 8 + wid;

    __shared__ float bsum;
    if (tid == 0) bsum = 0.0f;
    __syncthreads();

    const float4* dr4 = (const float4*)(g_dist + (size_t)row * N);
    const int4*   lb4 = (const int4*)labels;
    const float INF = __int_as_float(0x7f800000);

    // phase 1: per-lane sorted top-15 over 256 elems (64 float4)
    float loc[15];
#pragma unroll
    for (int q = 0; q < 15; q++) loc[q] = INF;
#pragma unroll 4
    for (int k = 0; k < 64; k++) {
        float4 v = dr4[lane + k * 32];
        ins15(loc, v.x); ins15(loc, v.y); ins15(loc, v.z); ins15(loc, v.w);
    }

    // phase 2: 15-round k-way warp merge (shfl min + ballot pop)
    float dmin = 0.0f, kth = 0.0f;
#pragma unroll
    for (int r = 0; r < 15; r++) {
        float h = loc[0];
        float m = h;
#pragma unroll
        for (int o = 16; o > 0; o >>= 1) m = fminf(m, __shfl_xor_sync(0xffffffffu, m, o));
        unsigned ball = __ballot_sync(0xffffffffu, h == m);
        int winner = __ffs(ball) - 1;
        if (lane == winner) {
#pragma unroll
            for (int q = 0; q < 14; q++) loc[q] = loc[q + 1];
            loc[14] = INF;
        }
        if (r == 0)  dmin = m;
        if (r == 14) kth  = m;
    }

    // phase 3: weights + per-batch accumulation (row re-read, likely L2-hot)
    float Z = 0.f, S = 0.f, s0 = 0.f, s1 = 0.f, s2 = 0.f;
#pragma unroll 2
    for (int k = 0; k < 64; k++) {
        float4 dv = dr4[lane + k * 32];
        int4   lb = lb4[lane + k * 32];
        float d, e, km, tt;
        d = dv.x; e = __expf(dmin - d); km = 1.0f / (1.0f + __expf(d - kth)); tt = e * km;
        Z += e; S += tt;
        s0 += (lb.x == 0) ? tt : 0.f; s1 += (lb.x == 1) ? tt : 0.f; s2 += (lb.x == 2) ? tt : 0.f;
        d = dv.y; e = __expf(dmin - d); km = 1.0f / (1.0f + __expf(d - kth)); tt = e * km;
        Z += e; S += tt;
        s0 += (lb.y == 0) ? tt : 0.f; s1 += (lb.y == 1) ? tt : 0.f; s2 += (lb.y == 2) ? tt : 0.f;
        d = dv.z; e = __expf(dmin - d); km = 1.0f / (1.0f + __expf(d - kth)); tt = e * km;
        Z += e; S += tt;
        s0 += (lb.z == 0) ? tt : 0.f; s1 += (lb.z == 1) ? tt : 0.f; s2 += (lb.z == 2) ? tt : 0.f;
        d = dv.w; e = __expf(dmin - d); km = 1.0f / (1.0f + __expf(d - kth)); tt = e * km;
        Z += e; S += tt;
        s0 += (lb.w == 0) ? tt : 0.f; s1 += (lb.w == 1) ? tt : 0.f; s2 += (lb.w == 2) ? tt : 0.f;
    }
#pragma unroll
    for (int o = 16; o > 0; o >>= 1) {
        Z  += __shfl_down_sync(0xffffffffu, Z,  o);
        S  += __shfl_down_sync(0xffffffffu, S,  o);
        s0 += __shfl_down_sync(0xffffffffu, s0, o);
        s1 += __shfl_down_sync(0xffffffffu, s1, o);
        s2 += __shfl_down_sync(0xffffffffu, s2, o);
    }
    if (lane == 0) {
        float denom = S + 1e-8f * Z;
        float p0 = s0 / denom, p1 = s1 / denom, p2 = s2 / denom;
        float H = -(p0 * logf(p0 + 1e-8f) + p1 * logf(p1 + 1e-8f) + p2 * logf(p2 + 1e-8f));
        float nH = H / (logf(3.0f) + 1e-8f);
        atomicAdd(&bsum, -nH * (1.0f / N));
    }
    __syncthreads();
    if (tid == 0) atomicAdd(out, bsum);
}

// ---------------------------------------------------------------------------
extern "C" void kernel_launch(void* const* d_in, const int* in_sizes, int n_in,
                              void* d_out, int out_size) {
    const float* emb    = (const float*)d_in[0];
    const int*   labels = (const int*)d_in[1];
    float*       out    = (float*)d_out;

    cudaFuncSetAttribute(gemm_kernel, cudaFuncAttributeMaxDynamicSharedMemorySize, GEMM_SMEM);

    prep_kernel<<<N / 8, 256>>>(emb, out);
    gemm_kernel<<<64 * 65 / 2, 256, GEMM_SMEM>>>();   // 2080 upper-tri tiles
    row_kernel<<<N / 8, 256>>>(labels, out);
}